// round 3
// baseline (speedup 1.0000x reference)
#include <cuda_runtime.h>

#define BB 64
#define EE 8978
#define E2C 4489
#define N1 (BB*EE)      // 574592
#define N2 (BB*E2C)     // 287296
#define SLOPE 0.33f
#define EPSBN 1e-5f

// ---------------- device scratch (allowed: __device__ globals) ----------------
__device__ float g_Tc1[N1];
__device__ float g_T21[N1];
__device__ float g_out32[18386944];   // N1*32 ; reused for layer1 pre-BN out (N2*32)
__device__ float g_xp  [9193472];     // N2*32 pooled input (T0 of layer1)
__device__ float g_Ta  [9193472];     // T1
__device__ float g_Tb  [9193472];     // T2
__device__ float g_Tcc [9193472];     // T3
__device__ float g_act1[9193472];     // activated layer1 out (T0 of layer2)
__device__ float g_z[N2];
__device__ float g_H1[64*256];
__device__ float g_H2[64*128];
__device__ double g_acc0[64];         // layer0 BN sums / sumsq (32+32)
__device__ double g_acc1[64];         // layer1
__device__ double g_acc2[2];          // layer2 (1 channel)
__device__ float g_scale0[32], g_shift0[32];
__device__ float g_scale1[32], g_shift1[32];
__device__ float g_scale2[1],  g_shift2[1];

// ---------------- init: zero accumulators each replay ----------------
__global__ void kZero() {
    int t = threadIdx.x;
    if (t < 64) g_acc0[t] = 0.0;
    else if (t < 128) g_acc1[t - 64] = 0.0;
    else if (t < 130) g_acc2[t - 128] = 0.0;
}

// ---------------- layer0: half-warp-per-node scalar matvec ----------------
// all lanes of each 16-lane half end up holding the half's sum
__device__ __forceinline__ float halfwarp_mv(const int* __restrict__ src,
                                             const float* __restrict__ ew,
                                             const float* __restrict__ v,
                                             int node, int lane) {
    int e = node * 16 + (lane & 15);
    float acc = ew[e] * v[src[e]];
#pragma unroll
    for (int off = 8; off; off >>= 1)
        acc += __shfl_xor_sync(0xffffffffu, acc, off);
    return acc;
}

__global__ void kA1(const float* __restrict__ x, const int* __restrict__ src,
                    const float* __restrict__ ew) {
    int warp = (blockIdx.x * blockDim.x + threadIdx.x) >> 5;
    int lane = threadIdx.x & 31;
    int node = warp * 2 + (lane >> 4);
    float y = halfwarp_mv(src, ew, x, node, lane);
    if ((lane & 15) == 0) g_Tc1[node] = x[node] - y;
}

__global__ void kA2(const float* __restrict__ x, const int* __restrict__ src,
                    const float* __restrict__ ew) {
    int warp = (blockIdx.x * blockDim.x + threadIdx.x) >> 5;
    int lane = threadIdx.x & 31;
    int node = warp * 2 + (lane >> 4);
    float y = halfwarp_mv(src, ew, g_Tc1, node, lane);
    if ((lane & 15) == 0)
        g_T21[node] = 0.5f * (3.0f * g_Tc1[node] - y - x[node]);
}

// matvec(T2) -> T3 ; out32 = outer([x,T1,T2,T3], W0)+b0 ; BN sums
__global__ void kA3(const float* __restrict__ x, const int* __restrict__ src,
                    const float* __restrict__ ew, const float* __restrict__ W0,
                    const float* __restrict__ b0) {
    int lane = threadIdx.x & 31;
    float w0 = W0[lane], w1 = W0[32 + lane], w2 = W0[64 + lane], w3 = W0[96 + lane];
    float bb = b0[lane];
    __shared__ float ssum[32], ssq[32];
    if (threadIdx.x < 32) { ssum[threadIdx.x] = 0.f; ssq[threadIdx.x] = 0.f; }
    __syncthreads();
    float lsum = 0.f, lsq = 0.f;
    int nwarps = (gridDim.x * blockDim.x) >> 5;
    int warp0 = (blockIdx.x * blockDim.x + threadIdx.x) >> 5;
    for (int p = warp0; p < N1 / 2; p += nwarps) {
        int node = p * 2 + (lane >> 4);
        float y  = halfwarp_mv(src, ew, g_T21, node, lane);
        float xv = x[node], tc = g_Tc1[node], t2 = g_T21[node];
        float t3 = (5.0f * t2 - y - 2.0f * tc) * (1.0f / 3.0f);
#pragma unroll
        for (int h = 0; h < 2; h++) {
            int sl = h * 16;
            float ax  = __shfl_sync(0xffffffffu, xv, sl);
            float atc = __shfl_sync(0xffffffffu, tc, sl);
            float at2 = __shfl_sync(0xffffffffu, t2, sl);
            float at3 = __shfl_sync(0xffffffffu, t3, sl);
            float o = ax * w0 + atc * w1 + at2 * w2 + at3 * w3 + bb;
            g_out32[(p * 2 + h) * 32 + lane] = o;
            lsum += o; lsq += o * o;
        }
    }
    atomicAdd(&ssum[lane], lsum);
    atomicAdd(&ssq[lane], lsq);
    __syncthreads();
    if (threadIdx.x < 32) {
        atomicAdd(&g_acc0[threadIdx.x], (double)ssum[threadIdx.x]);
        atomicAdd(&g_acc0[32 + threadIdx.x], (double)ssq[threadIdx.x]);
    }
}

// ---------------- BN finalize (tiny) ----------------
__global__ void kBNfin(const double* __restrict__ acc, const double* __restrict__ accsq,
                       const float* __restrict__ g, const float* __restrict__ be,
                       float* scale, float* shift, int nCh, double invN) {
    int c = threadIdx.x;
    if (c >= nCh) return;
    double mean = acc[c] * invN;
    double var  = accsq[c] * invN - mean * mean;
    float scl = g[c] * rsqrtf((float)var + EPSBN);
    scale[c] = scl;
    shift[c] = be[c] - (float)mean * scl;
}

// ---------------- pool: BN0 + LeakyReLU + pairwise max ----------------
__global__ void kPool() {
    int warp = (blockIdx.x * blockDim.x + threadIdx.x) >> 5;
    int lane = threadIdx.x & 31;
    float scale = g_scale0[lane], shift = g_shift0[lane];
    int b = warp / E2C, m = warp % E2C;
    int na = (b * EE + 2 * m) * 32 + lane;
    float va = g_out32[na] * scale + shift;       va = va > 0.f ? va : SLOPE * va;
    float vb = g_out32[na + 32] * scale + shift;  vb = vb > 0.f ? vb : SLOPE * vb;
    g_xp[warp * 32 + lane] = fmaxf(va, vb);
}

// ---------------- pooled-graph matvec: warp per node, lane = channel ----------
// out = ca*vin[row] + cb*p1[row] + cc*(L vin)[row]
__global__ void kMV(const float* __restrict__ vin, const float* __restrict__ p1,
                    const int* __restrict__ src, const float* __restrict__ ew,
                    float* __restrict__ out, float ca, float cb, float cc) {
    int warp = (blockIdx.x * blockDim.x + threadIdx.x) >> 5;
    int lane = threadIdx.x & 31;
    int node = warp;
    int e = node * 16 + (lane & 15);
    int s = src[e];
    float wv = ew[e];
    float acc = 0.f;
#pragma unroll
    for (int j = 0; j < 16; j++) {
        int   sj = __shfl_sync(0xffffffffu, s,  j);
        float wj = __shfl_sync(0xffffffffu, wv, j);
        acc += wj * vin[sj * 32 + lane];
    }
    float o = ca * vin[node * 32 + lane] + cc * acc;
    if (cb != 0.f) o += cb * p1[node * 32 + lane];
    out[node * 32 + lane] = o;
}

// ---------------- layer1 output GEMM: [T0|T1|T2|T3](N2x128) @ W1(128x32) -----
__global__ void kGemmOut1(const float* __restrict__ W1, const float* __restrict__ b1) {
    __shared__ float Wsh[128 * 32];
    __shared__ float Tsh[64 * 32];
    __shared__ float ssum[32], ssq[32];
    int tid = threadIdx.x, c = tid & 31, rg = tid >> 5;
    for (int i = tid; i < 4096; i += 256) Wsh[i] = W1[i];
    if (tid < 32) { ssum[tid] = 0.f; ssq[tid] = 0.f; }
    int n0 = blockIdx.x * 64;
    float acc[8];
#pragma unroll
    for (int q = 0; q < 8; q++) acc[q] = 0.f;
    const float* Tarr[4] = { g_xp, g_Ta, g_Tb, g_Tcc };
    for (int k = 0; k < 4; k++) {
        __syncthreads();
        const float* T = Tarr[k];
#pragma unroll
        for (int q = 0; q < 8; q++)
            Tsh[(rg + 8 * q) * 32 + c] = T[(n0 + rg + 8 * q) * 32 + c];
        __syncthreads();
#pragma unroll
        for (int i = 0; i < 32; i += 4) {
            float wa = Wsh[(k * 32 + i) * 32 + c];
            float wb = Wsh[(k * 32 + i + 1) * 32 + c];
            float wc = Wsh[(k * 32 + i + 2) * 32 + c];
            float wd = Wsh[(k * 32 + i + 3) * 32 + c];
#pragma unroll
            for (int q = 0; q < 8; q++) {
                float4 t = *(const float4*)&Tsh[(rg + 8 * q) * 32 + i];
                acc[q] += t.x * wa + t.y * wb + t.z * wc + t.w * wd;
            }
        }
    }
    float bv = b1[c];
    float lsum = 0.f, lsq = 0.f;
#pragma unroll
    for (int q = 0; q < 8; q++) {
        float o = acc[q] + bv;
        g_out32[(n0 + rg + 8 * q) * 32 + c] = o;
        lsum += o; lsq += o * o;
    }
    atomicAdd(&ssum[c], lsum);
    atomicAdd(&ssq[c], lsq);
    __syncthreads();
    if (tid < 32) {
        atomicAdd(&g_acc1[tid], (double)ssum[tid]);
        atomicAdd(&g_acc1[32 + tid], (double)ssq[tid]);
    }
}

// ---------------- layer1 activation ----------------
__global__ void kAct1() {
    int idx = blockIdx.x * 256 + threadIdx.x;   // N2*32 threads
    int c = idx & 31;
    float v = g_out32[idx] * g_scale1[c] + g_shift1[c];
    g_act1[idx] = v > 0.f ? v : SLOPE * v;
}

// ---------------- layer2 final step: matvec(T2)->T3, z = sum_k Tk.W2k + b2 ----
__global__ void kC3(const int* __restrict__ src, const float* __restrict__ ew,
                    const float* __restrict__ W2, const float* __restrict__ b2) {
    int lane = threadIdx.x & 31;
    float w2a = W2[lane], w2b = W2[32 + lane], w2c = W2[64 + lane], w2d = W2[96 + lane];
    float bv = b2[0];
    __shared__ float bs[2];
    if (threadIdx.x < 2) bs[threadIdx.x] = 0.f;
    __syncthreads();
    int nwarps = (gridDim.x * blockDim.x) >> 5;
    int warp0 = (blockIdx.x * blockDim.x + threadIdx.x) >> 5;
    float lsum = 0.f, lsq = 0.f;
    for (int node = warp0; node < N2; node += nwarps) {
        int e = node * 16 + (lane & 15);
        int s = src[e];
        float wv = ew[e];
        float acc = 0.f;
#pragma unroll
        for (int j = 0; j < 16; j++) {
            int   sj = __shfl_sync(0xffffffffu, s,  j);
            float wj = __shfl_sync(0xffffffffu, wv, j);
            acc += wj * g_Tb[sj * 32 + lane];
        }
        float t2 = g_Tb[node * 32 + lane];
        float t1 = g_Ta[node * 32 + lane];
        float t0 = g_act1[node * 32 + lane];
        float t3 = (5.f * t2 - acc - 2.f * t1) * (1.f / 3.f);
        float part = t0 * w2a + t1 * w2b + t2 * w2c + t3 * w2d;
#pragma unroll
        for (int off = 16; off; off >>= 1)
            part += __shfl_xor_sync(0xffffffffu, part, off);
        if (lane == 0) {
            float z = part + bv;
            g_z[node] = z;
            lsum += z; lsq += z * z;
        }
    }
    if (lane == 0) { atomicAdd(&bs[0], lsum); atomicAdd(&bs[1], lsq); }
    __syncthreads();
    if (threadIdx.x == 0) {
        atomicAdd(&g_acc2[0], (double)bs[0]);
        atomicAdd(&g_acc2[1], (double)bs[1]);
    }
}

// ---------------- MLP head ----------------
// D1: H1 = act2(z).reshape(64,E2C) @ lin1_W + lin1_b   (act2 = BN2 + LeakyReLU)
__global__ void kD1(const float* __restrict__ lin1W, const float* __restrict__ lin1b) {
    __shared__ float As[16][64];
    __shared__ float Ws[64][8];
    int tid = threadIdx.x;
    int c = tid & 7, r = tid >> 3;
    int c0 = (blockIdx.x & 31) * 8;
    int r0 = (blockIdx.x >> 5) * 16;
    float scale = g_scale2[0], shift = g_shift2[0];
    float acc = 0.f;
    for (int e0 = 0; e0 < E2C; e0 += 64) {
        __syncthreads();
        for (int t = tid; t < 1024; t += 128) {
            int rr = t >> 6, ii = t & 63, e = e0 + ii;
            float v = 0.f;
            if (e < E2C) {
                float z = g_z[(r0 + rr) * E2C + e] * scale + shift;
                v = z > 0.f ? z : SLOPE * z;
            }
            As[rr][ii] = v;
        }
        for (int t = tid; t < 512; t += 128) {
            int ii = t >> 3, cc = t & 7, e = e0 + ii;
            Ws[ii][cc] = (e < E2C) ? lin1W[e * 256 + c0 + cc] : 0.f;
        }
        __syncthreads();
#pragma unroll 8
        for (int i = 0; i < 64; i++) acc += As[r][i] * Ws[i][c];
    }
    g_H1[(r0 + r) * 256 + c0 + c] = acc + lin1b[c0 + c];
}

// D2: BN1(stats over 64 rows) + relu, H2 = a1 @ lin2_W + b
__global__ void kD2(const float* __restrict__ bn1g, const float* __restrict__ bn1b,
                    const float* __restrict__ lin2W, const float* __restrict__ lin2b) {
    __shared__ float sc[256], sh[256], As[2][256];
    int tid = threadIdx.x;
    {
        int col = tid;
        float s = 0.f, q = 0.f;
        for (int r = 0; r < 64; r++) { float v = g_H1[r * 256 + col]; s += v; q += v * v; }
        float mean = s * (1.f / 64.f);
        float var  = q * (1.f / 64.f) - mean * mean;
        float scl = bn1g[col] * rsqrtf(var + EPSBN);
        sc[col] = scl; sh[col] = bn1b[col] - mean * scl;
    }
    __syncthreads();
    int r0 = blockIdx.x * 2;
    for (int t = tid; t < 512; t += 256) {
        int rr = t >> 8, k = t & 255;
        float v = g_H1[(r0 + rr) * 256 + k] * sc[k] + sh[k];
        As[rr][k] = v > 0.f ? v : 0.f;
    }
    __syncthreads();
    int c = tid & 127, rr = tid >> 7;
    float acc = lin2b[c];
#pragma unroll 8
    for (int k = 0; k < 256; k++) acc += As[rr][k] * lin2W[k * 128 + c];
    g_H2[(r0 + rr) * 128 + c] = acc;
}

// D3: BN2 over H2 + relu + final linear -> d_out[64]
__global__ void kD3(const float* __restrict__ bn2g, const float* __restrict__ bn2b,
                    const float* __restrict__ lin3W, const float* __restrict__ lin3b,
                    float* __restrict__ out) {
    __shared__ float sc[128], sh[128];
    int tid = threadIdx.x;
    if (tid < 128) {
        float s = 0.f, q = 0.f;
        for (int r = 0; r < 64; r++) { float v = g_H2[r * 128 + tid]; s += v; q += v * v; }
        float mean = s * (1.f / 64.f);
        float var  = q * (1.f / 64.f) - mean * mean;
        float scl = bn2g[tid] * rsqrtf(var + EPSBN);
        sc[tid] = scl; sh[tid] = bn2b[tid] - mean * scl;
    }
    __syncthreads();
    int lane = tid & 31, w = tid >> 5;
    for (int r = w; r < 64; r += 8) {
        float acc = 0.f;
        for (int kk = lane; kk < 128; kk += 32) {
            float v = g_H2[r * 128 + kk] * sc[kk] + sh[kk];
            v = v > 0.f ? v : 0.f;
            acc += v * lin3W[kk];
        }
#pragma unroll
        for (int off = 16; off; off >>= 1)
            acc += __shfl_xor_sync(0xffffffffu, acc, off);
        if (lane == 0) out[r] = acc + lin3b[0];
    }
}

// ---------------- host launcher ----------------
extern "C" void kernel_launch(void* const* d_in, const int* in_sizes, int n_in,
                              void* d_out, int out_size) {
    const float* x    = (const float*)d_in[0];
    const int*   src1 = (const int*)  d_in[1];              // dst half unused (dst[e]==e/16)
    const float* ew1  = (const float*)d_in[2];
    const int*   src2 = (const int*)  d_in[3];
    const float* ew2  = (const float*)d_in[4];
    const float* W0 = (const float*)d_in[5];
    const float* b0 = (const float*)d_in[6];
    const float* g0 = (const float*)d_in[7];
    const float* be0= (const float*)d_in[8];
    const float* W1 = (const float*)d_in[9];
    const float* b1 = (const float*)d_in[10];
    const float* g1 = (const float*)d_in[11];
    const float* be1= (const float*)d_in[12];
    const float* W2 = (const float*)d_in[13];
    const float* b2 = (const float*)d_in[14];
    const float* g2 = (const float*)d_in[15];
    const float* be2= (const float*)d_in[16];
    const float* lin1W = (const float*)d_in[17];
    const float* lin1b = (const float*)d_in[18];
    const float* bn1g  = (const float*)d_in[19];
    const float* bn1b  = (const float*)d_in[20];
    const float* lin2W = (const float*)d_in[21];
    const float* lin2b = (const float*)d_in[22];
    const float* bn2g  = (const float*)d_in[23];
    const float* bn2b  = (const float*)d_in[24];
    const float* lin3W = (const float*)d_in[25];
    const float* lin3b = (const float*)d_in[26];
    float* out = (float*)d_out;

    double* acc0; double* acc1; double* acc2;
    float *sc0, *sf0, *sc1, *sf1, *sc2, *sf2;
    cudaGetSymbolAddress((void**)&acc0, g_acc0);
    cudaGetSymbolAddress((void**)&acc1, g_acc1);
    cudaGetSymbolAddress((void**)&acc2, g_acc2);
    cudaGetSymbolAddress((void**)&sc0, g_scale0);
    cudaGetSymbolAddress((void**)&sf0, g_shift0);
    cudaGetSymbolAddress((void**)&sc1, g_scale1);
    cudaGetSymbolAddress((void**)&sf1, g_shift1);
    cudaGetSymbolAddress((void**)&sc2, g_scale2);
    cudaGetSymbolAddress((void**)&sf2, g_shift2);
    float *pXp, *pTa, *pTb, *pTcc, *pAct1;
    cudaGetSymbolAddress((void**)&pXp,  g_xp);
    cudaGetSymbolAddress((void**)&pTa,  g_Ta);
    cudaGetSymbolAddress((void**)&pTb,  g_Tb);
    cudaGetSymbolAddress((void**)&pTcc, g_Tcc);
    cudaGetSymbolAddress((void**)&pAct1,g_act1);

    kZero<<<1, 256>>>();

    // ---- layer0 (1 channel, fine graph) ----
    kA1<<<N1 / 16, 256>>>(x, src1, ew1);
    kA2<<<N1 / 16, 256>>>(x, src1, ew1);
    kA3<<<1184, 256>>>(x, src1, ew1, W0, b0);
    kBNfin<<<1, 32>>>(acc0, acc0 + 32, g0, be0, sc0, sf0, 32, 1.0 / (double)N1);
    kPool<<<N2 / 8, 256>>>();

    // ---- layer1 (32 channels, pooled graph) ----
    kMV<<<N2 / 8, 256>>>(pXp, pXp, src2, ew2, pTa, 1.0f, 0.0f, -1.0f);
    kMV<<<N2 / 8, 256>>>(pTa, pXp, src2, ew2, pTb, 1.5f, -0.5f, -0.5f);
    kMV<<<N2 / 8, 256>>>(pTb, pTa, src2, ew2, pTcc, 5.f/3.f, -2.f/3.f, -1.f/3.f);
    kGemmOut1<<<N2 / 64, 256>>>(W1, b1);
    kBNfin<<<1, 32>>>(acc1, acc1 + 32, g1, be1, sc1, sf1, 32, 1.0 / (double)N2);
    kAct1<<<(N2 * 32) / 256, 256>>>();

    // ---- layer2 (32 -> 1) ----
    kMV<<<N2 / 8, 256>>>(pAct1, pAct1, src2, ew2, pTa, 1.0f, 0.0f, -1.0f);
    kMV<<<N2 / 8, 256>>>(pTa, pAct1, src2, ew2, pTb, 1.5f, -0.5f, -0.5f);
    kC3<<<1184, 256>>>(src2, ew2, W2, b2);
    kBNfin<<<1, 32>>>(acc2, acc2 + 1, g2, be2, sc2, sf2, 1, 1.0 / (double)N2);

    // ---- MLP head ----
    kD1<<<128, 128>>>(lin1W, lin1b);
    kD2<<<32, 256>>>(bn1g, bn1b, lin2W, lin2b);
    kD3<<<1, 256>>>(bn2g, bn2b, lin3W, lin3b, out);
}

// round 6
// speedup vs baseline: 1.2388x; 1.2388x over previous
#include <cuda_runtime.h>

#define BB 64
#define EE 8978
#define E2C 4489
#define N1 (BB*EE)      // 574592
#define N2 (BB*E2C)     // 287296
#define SLOPE 0.33f
#define EPSBN 1e-5f

// ---------------- device scratch ----------------
__device__ float g_out32[9193472];   // pooled pre-BN (N2*32), later layer1 pre-BN out (N2*32)
__device__ float g_xp  [9193472];    // act0 output = layer1 T0
__device__ float g_Ta  [9193472];    // layer1 T1
__device__ float g_Tb  [9193472];    // layer1 T2
__device__ float g_Tcc [9193472];    // layer1 T3
__device__ float g_Y [N2*4];         // layer2 projected field
__device__ float g_U1[N2*4];
__device__ float g_U2[N2*4];
__device__ float g_z[N2];
__device__ float g_H1[64*256];
__device__ float g_H2[64*128];
__device__ double g_acc0[64];
__device__ double g_acc1[64];
__device__ double g_acc2[2];
__device__ float g_scale0[32], g_shift0[32];
__device__ float g_scale1[32], g_shift1[32];
__device__ float g_scale2[1],  g_shift2[1];

// ---------------- init ----------------
__global__ void kZero() {
    int t = threadIdx.x;
    if (t < 64) g_acc0[t] = 0.0;
    else if (t < 128) g_acc1[t - 64] = 0.0;
    else if (t < 130) g_acc2[t - 128] = 0.0;
}

// ---------------- fused layer0: block per graph, fields in smem ----------------
// x, T1, T2 live in shared memory (36KB each). 3 Laguerre steps, then
// K-projection to 32 ch + pre-BN pairwise max pool + BN0 stat accumulation.
__global__ void kL0(const float* __restrict__ x, const int* __restrict__ src,
                    const float* __restrict__ ew, const float* __restrict__ W0,
                    const float* __restrict__ b0) {
    extern __shared__ float sm[];
    float* xs  = sm;
    float* t1s = sm + EE;
    float* t2s = sm + 2 * EE;
    __shared__ float s_sum[32], s_sq[32];

    int g = blockIdx.x;
    int tid = threadIdx.x;
    int lane = tid & 31, warp = tid >> 5;      // 32 warps of 1024 threads
    int nbase = g * EE;
    int ebase = nbase * 16;

    for (int i = tid; i < EE; i += 1024) xs[i] = x[nbase + i];
    if (tid < 32) { s_sum[tid] = 0.f; s_sq[tid] = 0.f; }
    __syncthreads();

    // step1: T1 = x - L x   (warp per node-pair, halfwarp per node)
    for (int p = warp; p < E2C; p += 32) {
        int e = ebase + p * 32 + lane;
        int ls = src[e] - nbase;
        float a = ew[e] * xs[ls];
        a += __shfl_xor_sync(~0u, a, 8);
        a += __shfl_xor_sync(~0u, a, 4);
        a += __shfl_xor_sync(~0u, a, 2);
        a += __shfl_xor_sync(~0u, a, 1);
        if (lane == 0)  t1s[2 * p]     = xs[2 * p]     - a;
        if (lane == 16) t1s[2 * p + 1] = xs[2 * p + 1] - a;
    }
    __syncthreads();

    // step2: T2 = (3 T1 - L T1 - x) / 2
    for (int p = warp; p < E2C; p += 32) {
        int e = ebase + p * 32 + lane;
        int ls = src[e] - nbase;
        float a = ew[e] * t1s[ls];
        a += __shfl_xor_sync(~0u, a, 8);
        a += __shfl_xor_sync(~0u, a, 4);
        a += __shfl_xor_sync(~0u, a, 2);
        a += __shfl_xor_sync(~0u, a, 1);
        if (lane == 0)  t2s[2 * p]     = 0.5f * (3.f * t1s[2 * p]     - a - xs[2 * p]);
        if (lane == 16) t2s[2 * p + 1] = 0.5f * (3.f * t1s[2 * p + 1] - a - xs[2 * p + 1]);
    }
    __syncthreads();

    // step3: T3 = (5 T2 - L T2 - 2 T1)/3 ; project to 32 ch; pre-BN max pool
    float w0 = W0[lane], w1 = W0[32 + lane], w2 = W0[64 + lane], w3 = W0[96 + lane];
    float bb = b0[lane];
    float lsum = 0.f, lsq = 0.f;
    for (int p = warp; p < E2C; p += 32) {
        int e = ebase + p * 32 + lane;
        int ls = src[e] - nbase;
        float a = ew[e] * t2s[ls];
        a += __shfl_xor_sync(~0u, a, 8);
        a += __shfl_xor_sync(~0u, a, 4);
        a += __shfl_xor_sync(~0u, a, 2);
        a += __shfl_xor_sync(~0u, a, 1);
        float t3 = 0.f;
        if ((lane & 15) == 0) {
            int n = 2 * p + (lane >> 4);
            t3 = (5.f * t2s[n] - a - 2.f * t1s[n]) * (1.f / 3.f);
        }
        float t3a = __shfl_sync(~0u, t3, 0);
        float t3b = __shfl_sync(~0u, t3, 16);
        float xa  = xs[2 * p],  xb  = xs[2 * p + 1];
        float ta1 = t1s[2 * p], tb1 = t1s[2 * p + 1];
        float ta2 = t2s[2 * p], tb2 = t2s[2 * p + 1];
        // lane = channel here
        float oa = fmaf(xa, w0, fmaf(ta1, w1, fmaf(ta2, w2, fmaf(t3a, w3, bb))));
        float ob = fmaf(xb, w0, fmaf(tb1, w1, fmaf(tb2, w2, fmaf(t3b, w3, bb))));
        lsum += oa + ob;
        lsq  += oa * oa + ob * ob;
        g_out32[((size_t)(g * E2C + p)) * 32 + lane] = fmaxf(oa, ob);
    }
    atomicAdd(&s_sum[lane], lsum);
    atomicAdd(&s_sq[lane], lsq);
    __syncthreads();
    if (tid < 32) {
        atomicAdd(&g_acc0[tid],      (double)s_sum[tid]);
        atomicAdd(&g_acc0[32 + tid], (double)s_sq[tid]);
    }
}

// ---------------- BN finalize ----------------
__global__ void kBNfin(const double* __restrict__ acc, const double* __restrict__ accsq,
                       const float* __restrict__ g, const float* __restrict__ be,
                       float* scale, float* shift, int nCh, double invN) {
    int c = threadIdx.x;
    if (c >= nCh) return;
    double mean = acc[c] * invN;
    double var  = accsq[c] * invN - mean * mean;
    float scl = g[c] * rsqrtf((float)var + EPSBN);
    scale[c] = scl;
    shift[c] = be[c] - (float)mean * scl;
}

// ---------------- act0: BN0 + LeakyReLU on pooled values ----------------
__global__ void kAct0() {
    int i = blockIdx.x * 256 + threadIdx.x;
    int c = i & 31;
    float v = g_out32[i] * g_scale0[c] + g_shift0[c];
    g_xp[i] = v > 0.f ? v : SLOPE * v;
}

// ---------------- pooled-graph 32-ch matvec (layer1) ----------------
__global__ void kMV(const float* __restrict__ vin, const float* __restrict__ p1,
                    const int* __restrict__ src, const float* __restrict__ ew,
                    float* __restrict__ out, float ca, float cb, float cc) {
    int warp = (blockIdx.x * blockDim.x + threadIdx.x) >> 5;
    int lane = threadIdx.x & 31;
    int node = warp;
    int e = node * 16 + (lane & 15);
    int s = src[e];
    float wv = ew[e];
    float acc = 0.f;
#pragma unroll
    for (int j = 0; j < 16; j++) {
        int   sj = __shfl_sync(0xffffffffu, s,  j);
        float wj = __shfl_sync(0xffffffffu, wv, j);
        acc += wj * vin[sj * 32 + lane];
    }
    float o = ca * vin[node * 32 + lane] + cc * acc;
    if (cb != 0.f) o += cb * p1[node * 32 + lane];
    out[node * 32 + lane] = o;
}

// ---------------- layer1 output GEMM + BN1 stats ----------------
__global__ void kGemmOut1(const float* __restrict__ W1, const float* __restrict__ b1) {
    __shared__ float Wsh[128 * 32];
    __shared__ float Tsh[64 * 32];
    __shared__ float ssum[32], ssq[32];
    int tid = threadIdx.x, c = tid & 31, rg = tid >> 5;
    for (int i = tid; i < 4096; i += 256) Wsh[i] = W1[i];
    if (tid < 32) { ssum[tid] = 0.f; ssq[tid] = 0.f; }
    int n0 = blockIdx.x * 64;
    float acc[8];
#pragma unroll
    for (int q = 0; q < 8; q++) acc[q] = 0.f;
    const float* Tarr[4] = { g_xp, g_Ta, g_Tb, g_Tcc };
    for (int k = 0; k < 4; k++) {
        __syncthreads();
        const float* T = Tarr[k];
#pragma unroll
        for (int q = 0; q < 8; q++)
            Tsh[(rg + 8 * q) * 32 + c] = T[(n0 + rg + 8 * q) * 32 + c];
        __syncthreads();
#pragma unroll
        for (int i = 0; i < 32; i += 4) {
            float wa = Wsh[(k * 32 + i) * 32 + c];
            float wb = Wsh[(k * 32 + i + 1) * 32 + c];
            float wc = Wsh[(k * 32 + i + 2) * 32 + c];
            float wd = Wsh[(k * 32 + i + 3) * 32 + c];
#pragma unroll
            for (int q = 0; q < 8; q++) {
                float4 t = *(const float4*)&Tsh[(rg + 8 * q) * 32 + i];
                acc[q] += t.x * wa + t.y * wb + t.z * wc + t.w * wd;
            }
        }
    }
    float bv = b1[c];
    float lsum = 0.f, lsq = 0.f;
#pragma unroll
    for (int q = 0; q < 8; q++) {
        float o = acc[q] + bv;
        g_out32[(n0 + rg + 8 * q) * 32 + c] = o;
        lsum += o; lsq += o * o;
    }
    atomicAdd(&ssum[c], lsum);
    atomicAdd(&ssq[c], lsq);
    __syncthreads();
    if (tid < 32) {
        atomicAdd(&g_acc1[tid], (double)ssum[tid]);
        atomicAdd(&g_acc1[32 + tid], (double)ssq[tid]);
    }
}

// ---------------- layer2 input: BN1 + LeakyReLU + project to 4 channels -------
// y_k[n] = sum_c act1[n,c] * W2[k,c]  (W2 commutes with L per-channel)
__global__ void kAct1Y(const float* __restrict__ W2) {
    int warp = (blockIdx.x * blockDim.x + threadIdx.x) >> 5;   // = node
    int lane = threadIdx.x & 31;
    float o = g_out32[warp * 32 + lane];
    float v = o * g_scale1[lane] + g_shift1[lane];
    v = v > 0.f ? v : SLOPE * v;
    float y0, y1, y2, y3;
    {
        float p = v * W2[lane];
#pragma unroll
        for (int off = 16; off; off >>= 1) p += __shfl_xor_sync(~0u, p, off);
        y0 = p;
    }
    {
        float p = v * W2[32 + lane];
#pragma unroll
        for (int off = 16; off; off >>= 1) p += __shfl_xor_sync(~0u, p, off);
        y1 = p;
    }
    {
        float p = v * W2[64 + lane];
#pragma unroll
        for (int off = 16; off; off >>= 1) p += __shfl_xor_sync(~0u, p, off);
        y2 = p;
    }
    {
        float p = v * W2[96 + lane];
#pragma unroll
        for (int off = 16; off; off >>= 1) p += __shfl_xor_sync(~0u, p, off);
        y3 = p;
    }
    if (lane < 4) {
        float val = (lane == 0) ? y0 : (lane == 1) ? y1 : (lane == 2) ? y2 : y3;
        g_Y[warp * 4 + lane] = val;
    }
}

// ---------------- 4-channel matvec on Y-field (layer2 recurrence) -------------
// block = 64 nodes; edges staged in smem (transposed, padded stride 65)
__global__ void kMVY(const float* __restrict__ vin, const float* __restrict__ p1,
                     const int* __restrict__ src, const float* __restrict__ ew,
                     float* __restrict__ out, float ca, float cb, float cc) {
    __shared__ int   s_src[16 * 65];
    __shared__ float s_ew [16 * 65];
    int tid = threadIdx.x;
    int e0 = blockIdx.x * 1024;
#pragma unroll
    for (int t = tid; t < 1024; t += 256) {
        int j = t & 15, local = t >> 4;
        s_src[j * 65 + local] = src[e0 + t];
        s_ew [j * 65 + local] = ew [e0 + t];
    }
    __syncthreads();
    int lane = tid & 31;
    int local = (tid >> 5) * 8 + (lane >> 2);   // node within block
    int ch = lane & 3;
    int node = blockIdx.x * 64 + local;
    float acc = 0.f;
#pragma unroll
    for (int j = 0; j < 16; j++) {
        int s   = s_src[j * 65 + local];
        float w = s_ew [j * 65 + local];
        acc += w * vin[s * 4 + ch];
    }
    float o = ca * vin[node * 4 + ch] + cc * acc;
    if (cb != 0.f) o += cb * p1[node * 4 + ch];
    out[node * 4 + ch] = o;
}

// final layer2 step: u3 = (5 U2 - L U2 - 2 U1)/3 ; z = Y0 + U1_1 + U2_2 + u3_3 + b2
__global__ void kMVY3C(const int* __restrict__ src, const float* __restrict__ ew,
                       const float* __restrict__ b2) {
    __shared__ int   s_src[16 * 65];
    __shared__ float s_ew [16 * 65];
    __shared__ float bs[2];
    int tid = threadIdx.x;
    int e0 = blockIdx.x * 1024;
    if (tid < 2) bs[tid] = 0.f;
#pragma unroll
    for (int t = tid; t < 1024; t += 256) {
        int j = t & 15, local = t >> 4;
        s_src[j * 65 + local] = src[e0 + t];
        s_ew [j * 65 + local] = ew [e0 + t];
    }
    __syncthreads();
    int lane = tid & 31;
    int local = (tid >> 5) * 8 + (lane >> 2);
    int ch = lane & 3;
    int node = blockIdx.x * 64 + local;
    float acc = 0.f;
#pragma unroll
    for (int j = 0; j < 16; j++) {
        int s   = s_src[j * 65 + local];
        float w = s_ew [j * 65 + local];
        acc += w * g_U2[s * 4 + ch];
    }
    float u2v = g_U2[node * 4 + ch];
    float u1v = g_U1[node * 4 + ch];
    float yv  = g_Y [node * 4 + ch];
    float u3  = (5.f * u2v - acc - 2.f * u1v) * (1.f / 3.f);
    int base = lane & ~3;
    float zY  = __shfl_sync(~0u, yv,  base + 0);
    float zU1 = __shfl_sync(~0u, u1v, base + 1);
    float zU2 = __shfl_sync(~0u, u2v, base + 2);
    float zU3 = __shfl_sync(~0u, u3,  base + 3);
    if (ch == 0) {
        float z = zY + zU1 + zU2 + zU3 + b2[0];
        g_z[node] = z;
        atomicAdd(&bs[0], z);
        atomicAdd(&bs[1], z * z);
    }
    __syncthreads();
    if (tid == 0) {
        atomicAdd(&g_acc2[0], (double)bs[0]);
        atomicAdd(&g_acc2[1], (double)bs[1]);
    }
}

// ---------------- MLP head ----------------
__global__ void kD1(const float* __restrict__ lin1W, const float* __restrict__ lin1b) {
    __shared__ float As[16][64];
    __shared__ float Ws[64][8];
    int tid = threadIdx.x;
    int c = tid & 7, r = tid >> 3;
    int c0 = (blockIdx.x & 31) * 8;
    int r0 = (blockIdx.x >> 5) * 16;
    float scale = g_scale2[0], shift = g_shift2[0];
    float acc = 0.f;
    for (int e0 = 0; e0 < E2C; e0 += 64) {
        __syncthreads();
        for (int t = tid; t < 1024; t += 128) {
            int rr = t >> 6, ii = t & 63, e = e0 + ii;
            float v = 0.f;
            if (e < E2C) {
                float z = g_z[(r0 + rr) * E2C + e] * scale + shift;
                v = z > 0.f ? z : SLOPE * z;
            }
            As[rr][ii] = v;
        }
        for (int t = tid; t < 512; t += 128) {
            int ii = t >> 3, cc = t & 7, e = e0 + ii;
            Ws[ii][cc] = (e < E2C) ? lin1W[e * 256 + c0 + cc] : 0.f;
        }
        __syncthreads();
#pragma unroll 8
        for (int i = 0; i < 64; i++) acc += As[r][i] * Ws[i][c];
    }
    g_H1[(r0 + r) * 256 + c0 + c] = acc + lin1b[c0 + c];
}

__global__ void kD2(const float* __restrict__ bn1g, const float* __restrict__ bn1b,
                    const float* __restrict__ lin2W, const float* __restrict__ lin2b) {
    __shared__ float sc[256], sh[256], As[2][256];
    int tid = threadIdx.x;
    {
        int col = tid;
        float s = 0.f, q = 0.f;
        for (int r = 0; r < 64; r++) { float v = g_H1[r * 256 + col]; s += v; q += v * v; }
        float mean = s * (1.f / 64.f);
        float var  = q * (1.f / 64.f) - mean * mean;
        float scl = bn1g[col] * rsqrtf(var + EPSBN);
        sc[col] = scl; sh[col] = bn1b[col] - mean * scl;
    }
    __syncthreads();
    int r0 = blockIdx.x * 2;
    for (int t = tid; t < 512; t += 256) {
        int rr = t >> 8, k = t & 255;
        float v = g_H1[(r0 + rr) * 256 + k] * sc[k] + sh[k];
        As[rr][k] = v > 0.f ? v : 0.f;
    }
    __syncthreads();
    int c = tid & 127, rr = tid >> 7;
    float acc = lin2b[c];
#pragma unroll 8
    for (int k = 0; k < 256; k++) acc += As[rr][k] * lin2W[k * 128 + c];
    g_H2[(r0 + rr) * 128 + c] = acc;
}

__global__ void kD3(const float* __restrict__ bn2g, const float* __restrict__ bn2b,
                    const float* __restrict__ lin3W, const float* __restrict__ lin3b,
                    float* __restrict__ out) {
    __shared__ float sc[128], sh[128];
    int tid = threadIdx.x;
    if (tid < 128) {
        float s = 0.f, q = 0.f;
        for (int r = 0; r < 64; r++) { float v = g_H2[r * 128 + tid]; s += v; q += v * v; }
        float mean = s * (1.f / 64.f);
        float var  = q * (1.f / 64.f) - mean * mean;
        float scl = bn2g[tid] * rsqrtf(var + EPSBN);
        sc[tid] = scl; sh[tid] = bn2b[tid] - mean * scl;
    }
    __syncthreads();
    int lane = tid & 31, w = tid >> 5;
    for (int r = w; r < 64; r += 8) {
        float acc = 0.f;
        for (int kk = lane; kk < 128; kk += 32) {
            float v = g_H2[r * 128 + kk] * sc[kk] + sh[kk];
            v = v > 0.f ? v : 0.f;
            acc += v * lin3W[kk];
        }
#pragma unroll
        for (int off = 16; off; off >>= 1)
            acc += __shfl_xor_sync(0xffffffffu, acc, off);
        if (lane == 0) out[r] = acc + lin3b[0];
    }
}

// ---------------- host launcher ----------------
extern "C" void kernel_launch(void* const* d_in, const int* in_sizes, int n_in,
                              void* d_out, int out_size) {
    const float* x    = (const float*)d_in[0];
    const int*   src1 = (const int*)  d_in[1];
    const float* ew1  = (const float*)d_in[2];
    const int*   src2 = (const int*)  d_in[3];
    const float* ew2  = (const float*)d_in[4];
    const float* W0 = (const float*)d_in[5];
    const float* b0 = (const float*)d_in[6];
    const float* g0 = (const float*)d_in[7];
    const float* be0= (const float*)d_in[8];
    const float* W1 = (const float*)d_in[9];
    const float* b1 = (const float*)d_in[10];
    const float* g1 = (const float*)d_in[11];
    const float* be1= (const float*)d_in[12];
    const float* W2 = (const float*)d_in[13];
    const float* b2 = (const float*)d_in[14];
    const float* g2 = (const float*)d_in[15];
    const float* be2= (const float*)d_in[16];
    const float* lin1W = (const float*)d_in[17];
    const float* lin1b = (const float*)d_in[18];
    const float* bn1g  = (const float*)d_in[19];
    const float* bn1b  = (const float*)d_in[20];
    const float* lin2W = (const float*)d_in[21];
    const float* lin2b = (const float*)d_in[22];
    const float* bn2g  = (const float*)d_in[23];
    const float* bn2b  = (const float*)d_in[24];
    const float* lin3W = (const float*)d_in[25];
    const float* lin3b = (const float*)d_in[26];
    float* out = (float*)d_out;

    double *acc0, *acc1, *acc2;
    float *sc0, *sf0, *sc1, *sf1, *sc2, *sf2;
    cudaGetSymbolAddress((void**)&acc0, g_acc0);
    cudaGetSymbolAddress((void**)&acc1, g_acc1);
    cudaGetSymbolAddress((void**)&acc2, g_acc2);
    cudaGetSymbolAddress((void**)&sc0, g_scale0);
    cudaGetSymbolAddress((void**)&sf0, g_shift0);
    cudaGetSymbolAddress((void**)&sc1, g_scale1);
    cudaGetSymbolAddress((void**)&sf1, g_shift1);
    cudaGetSymbolAddress((void**)&sc2, g_scale2);
    cudaGetSymbolAddress((void**)&sf2, g_shift2);
    float *pXp, *pTa, *pTb, *pTcc, *pY, *pU1, *pU2;
    cudaGetSymbolAddress((void**)&pXp,  g_xp);
    cudaGetSymbolAddress((void**)&pTa,  g_Ta);
    cudaGetSymbolAddress((void**)&pTb,  g_Tb);
    cudaGetSymbolAddress((void**)&pTcc, g_Tcc);
    cudaGetSymbolAddress((void**)&pY,   g_Y);
    cudaGetSymbolAddress((void**)&pU1,  g_U1);
    cudaGetSymbolAddress((void**)&pU2,  g_U2);

    const int kL0smem = 3 * EE * (int)sizeof(float);   // 107,736 bytes
    cudaFuncSetAttribute(kL0, cudaFuncAttributeMaxDynamicSharedMemorySize, kL0smem);

    kZero<<<1, 256>>>();

    // ---- layer0 fused (1 channel, fine graph, smem-resident) ----
    kL0<<<BB, 1024, kL0smem>>>(x, src1, ew1, W0, b0);
    kBNfin<<<1, 32>>>(acc0, acc0 + 32, g0, be0, sc0, sf0, 32, 1.0 / (double)N1);
    kAct0<<<(N2 * 32) / 256, 256>>>();

    // ---- layer1 (32 channels, pooled graph) ----
    kMV<<<N2 / 8, 256>>>(pXp, pXp, src2, ew2, pTa, 1.0f, 0.0f, -1.0f);
    kMV<<<N2 / 8, 256>>>(pTa, pXp, src2, ew2, pTb, 1.5f, -0.5f, -0.5f);
    kMV<<<N2 / 8, 256>>>(pTb, pTa, src2, ew2, pTcc, 5.f/3.f, -2.f/3.f, -1.f/3.f);
    kGemmOut1<<<N2 / 64, 256>>>(W1, b1);
    kBNfin<<<1, 32>>>(acc1, acc1 + 32, g1, be1, sc1, sf1, 32, 1.0 / (double)N2);

    // ---- layer2 collapsed to 4-channel recurrence ----
    kAct1Y<<<N2 / 8, 256>>>(W2);
    kMVY<<<N2 / 64, 256>>>(pY,  pY, src2, ew2, pU1, 1.0f, 0.0f, -1.0f);
    kMVY<<<N2 / 64, 256>>>(pU1, pY, src2, ew2, pU2, 1.5f, -0.5f, -0.5f);
    kMVY3C<<<N2 / 64, 256>>>(src2, ew2, b2);
    kBNfin<<<1, 32>>>(acc2, acc2 + 1, g2, be2, sc2, sf2, 1, 1.0 / (double)N2);

    // ---- MLP head ----
    kD1<<<128, 128>>>(lin1W, lin1b);
    kD2<<<32, 256>>>(bn1g, bn1b, lin2W, lin2b);
    kD3<<<1, 256>>>(bn2g, bn2b, lin3W, lin3b, out);
}